// round 1
// baseline (speedup 1.0000x reference)
#include <cuda_runtime.h>
#include <cuda_bf16.h>

// DataWindowLoss: mean(|box5(x) - box5(y)|), x,y: [64,1,512,512] f32.
// box5 = 5x5 uniform conv, padding 4 -> output [64,1,516,516].
// Linearity: box5(x)-box5(y) = box5(x-y). Separable sliding-window sums.

#define B_IMGS 64
#define H 512
#define W 512
#define OH 516
#define OW 516

#define OUT_ROWS 16            // output rows per block
#define IN_ROWS  (OUT_ROWS+4)  // 20 input rows (incl. 4-row halo)
#define DP 520                 // d-tile pitch: 4 front guard + 512 + 4 back guard
#define HP 516                 // hrow-tile pitch
#define ROW_TILES 33           // ceil(516/16)
#define NBLOCKS (B_IMGS * ROW_TILES)   // 2112
#define THREADS 256
#define SMEM_FLOATS (IN_ROWS*DP + IN_ROWS*HP)
#define SMEM_BYTES  (SMEM_FLOATS * sizeof(float))

__device__ float g_partials[4096];

__device__ __forceinline__ float warp_red(float v) {
    #pragma unroll
    for (int o = 16; o > 0; o >>= 1) v += __shfl_down_sync(0xffffffffu, v, o);
    return v;
}

__global__ void __launch_bounds__(THREADS)
box_abs_kernel(const float* __restrict__ x, const float* __restrict__ y) {
    extern __shared__ float sm[];
    float* dsm = sm;                    // IN_ROWS x DP  (d = x - y, guarded)
    float* hsm = sm + IN_ROWS * DP;     // IN_ROWS x HP  (horizontal 5-sums)

    const int tid  = threadIdx.x;
    const int tile = blockIdx.x;        // 0..32
    const int img  = blockIdx.y;        // 0..63
    const int r0   = tile * OUT_ROWS;   // first output row of this block

    const float* xi = x + (size_t)img * H * W;
    const float* yi = y + (size_t)img * H * W;

    // ---- Phase 1: load d = x - y into smem (float4), zero out-of-range rows ----
    for (int idx = tid; idx < IN_ROWS * (W / 4); idx += THREADS) {
        int ii = idx >> 7;              // row within tile (W/4 == 128)
        int jj = (idx & 127) << 2;      // column (float index)
        int gi = r0 - 4 + ii;           // global input row
        float4 v = make_float4(0.f, 0.f, 0.f, 0.f);
        if (gi >= 0 && gi < H) {
            const float4 a = *reinterpret_cast<const float4*>(xi + (size_t)gi * W + jj);
            const float4 b = *reinterpret_cast<const float4*>(yi + (size_t)gi * W + jj);
            v.x = a.x - b.x; v.y = a.y - b.y; v.z = a.z - b.z; v.w = a.w - b.w;
        }
        *reinterpret_cast<float4*>(dsm + ii * DP + 4 + jj) = v;
    }
    // zero the 4-float guard columns on both sides of every row
    if (tid < 2 * IN_ROWS) {
        int ii = tid >> 1;
        int off = (tid & 1) ? (4 + W) : 0;
        *reinterpret_cast<float4*>(dsm + ii * DP + off) = make_float4(0.f, 0.f, 0.f, 0.f);
    }
    __syncthreads();

    // ---- Phase 2: horizontal 5-tap sliding sums, 12 segments x 43 cols = 516 ----
    if (tid < IN_ROWS * 12) {
        int ii = tid / 12;
        int s  = tid - ii * 12;
        int c0 = s * 43;
        const float* dr = dsm + ii * DP;   // dr[c + k], k=0..4 == d(c-4..c)
        float*       hr = hsm + ii * HP;
        float w = dr[c0] + dr[c0 + 1] + dr[c0 + 2] + dr[c0 + 3] + dr[c0 + 4];
        hr[c0] = w;
        #pragma unroll 4
        for (int c = c0 + 1; c < c0 + 43; ++c) {
            w += dr[c + 4] - dr[c - 1];
            hr[c] = w;
        }
    }
    __syncthreads();

    // ---- Phase 3: vertical 5-tap sliding sums + |.| accumulation ----
    float acc = 0.f;
    const int rmax = min(OUT_ROWS, OH - r0);
    for (int c = tid; c < OW; c += THREADS) {
        float v = hsm[c] + hsm[HP + c] + hsm[2 * HP + c] + hsm[3 * HP + c] + hsm[4 * HP + c];
        acc += fabsf(v);
        #pragma unroll 5
        for (int rr = 1; rr < rmax; ++rr) {
            v += hsm[(rr + 4) * HP + c] - hsm[(rr - 1) * HP + c];
            acc += fabsf(v);
        }
    }

    // ---- Phase 4: block reduce, write deterministic per-block partial ----
    __shared__ float wsum[8];
    acc = warp_red(acc);
    if ((tid & 31) == 0) wsum[tid >> 5] = acc;
    __syncthreads();
    if (tid < 8) {
        float v = wsum[tid];
        v += __shfl_down_sync(0x000000ffu, v, 4);
        v += __shfl_down_sync(0x000000ffu, v, 2);
        v += __shfl_down_sync(0x000000ffu, v, 1);
        if (tid == 0) g_partials[img * ROW_TILES + tile] = v;
    }
}

__global__ void __launch_bounds__(256)
finalize_kernel(float* __restrict__ out) {
    __shared__ double sd[256];
    const int tid = threadIdx.x;
    double s = 0.0;
    for (int i = tid; i < NBLOCKS; i += 256) s += (double)g_partials[i];
    sd[tid] = s;
    __syncthreads();
    #pragma unroll
    for (int stride = 128; stride > 0; stride >>= 1) {
        if (tid < stride) sd[tid] += sd[tid + stride];
        __syncthreads();
    }
    if (tid == 0) {
        const double scale = 1.0 / (25.0 * (double)B_IMGS * (double)OH * (double)OW);
        out[0] = (float)(sd[0] * scale);
    }
}

extern "C" void kernel_launch(void* const* d_in, const int* in_sizes, int n_in,
                              void* d_out, int out_size) {
    (void)in_sizes; (void)n_in; (void)out_size;
    const float* x = (const float*)d_in[0];
    const float* y = (const float*)d_in[1];
    float* out = (float*)d_out;

    cudaFuncSetAttribute(box_abs_kernel,
                         cudaFuncAttributeMaxDynamicSharedMemorySize, SMEM_BYTES);

    dim3 grid(ROW_TILES, B_IMGS);
    box_abs_kernel<<<grid, THREADS, SMEM_BYTES>>>(x, y);
    finalize_kernel<<<1, 256>>>(out);
}

// round 2
// speedup vs baseline: 1.1485x; 1.1485x over previous
#include <cuda_runtime.h>
#include <cuda_bf16.h>

// DataWindowLoss: mean(|box5(x) - box5(y)|), x,y: [64,1,512,512] f32.
// box5(x)-box5(y) = box5(x-y); 5x5 uniform kernel is separable.
// Single fused kernel:
//   load d=x-y (float4) + horizontal 5-tap sum via warp shuffle -> smem h tile
//   vertical 5-tap sliding sum + |.| accumulate (float4)
//   block partial -> global double accumulator; last block writes scalar out.

#define B_IMGS 64
#define H 512
#define W 512
#define OH 516
#define OW 516

#define OUT_ROWS 16            // output rows per block
#define IN_ROWS  (OUT_ROWS+4)  // 20 h-rows (incl. 4-row halo)
#define HP 520                 // h-tile pitch in floats (516 + pad, %4==0)
#define ROW_TILES 33           // ceil(516/16)
#define NBLOCKS (B_IMGS * ROW_TILES)   // 2112
#define THREADS 256
#define NWARPS (THREADS/32)
#define GROUPS 129             // float4 groups of h per row (516 cols)
#define SEGS_PER_ROW 5         // ceil(129/32)
#define TOTAL_SEGS (IN_ROWS * SEGS_PER_ROW)  // 100
#define SMEM_BYTES (IN_ROWS * HP * 4)        // 41600

__device__ double g_accum;      // zero-initialized
__device__ unsigned g_count;    // zero-initialized

__device__ __forceinline__ float warp_red(float v) {
    #pragma unroll
    for (int o = 16; o > 0; o >>= 1) v += __shfl_down_sync(0xffffffffu, v, o);
    return v;
}

__global__ void __launch_bounds__(THREADS)
box_abs_kernel(const float* __restrict__ x, const float* __restrict__ y,
               float* __restrict__ out) {
    extern __shared__ float hsm[];  // IN_ROWS x HP  (horizontal 5-sums)

    const int tid  = threadIdx.x;
    const int lane = tid & 31;
    const int wi   = tid >> 5;
    const int tile = blockIdx.x;        // 0..32
    const int img  = blockIdx.y;        // 0..63
    const int r0   = tile * OUT_ROWS;   // first output row of this block

    const float4* x4 = reinterpret_cast<const float4*>(x) + (size_t)img * H * (W/4);
    const float4* y4 = reinterpret_cast<const float4*>(y) + (size_t)img * H * (W/4);

    // ---- Phase 1+2 fused: load d, horizontal 5-sum via shuffle, store h ----
    for (int seg = wi; seg < TOTAL_SEGS; seg += NWARPS) {
        const int ii = seg / SEGS_PER_ROW;       // h-row within tile
        const int s  = seg - ii * SEGS_PER_ROW;  // segment within row
        const int g  = s * 32 + lane;            // float4 group of h (0..128 valid)
        const int gi = r0 - 4 + ii;              // global input row
        const bool rowok = (gi >= 0) && (gi < H);
        const size_t rb = rowok ? ((size_t)gi * (W/4)) : 0;

        float4 cur = make_float4(0.f, 0.f, 0.f, 0.f);
        if (rowok && g < 128) {
            float4 a = x4[rb + g], b = y4[rb + g];
            cur.x = a.x - b.x; cur.y = a.y - b.y; cur.z = a.z - b.z; cur.w = a.w - b.w;
        }
        float4 prev;
        prev.x = __shfl_up_sync(0xffffffffu, cur.x, 1);
        prev.y = __shfl_up_sync(0xffffffffu, cur.y, 1);
        prev.z = __shfl_up_sync(0xffffffffu, cur.z, 1);
        prev.w = __shfl_up_sync(0xffffffffu, cur.w, 1);
        if (lane == 0) {
            prev = make_float4(0.f, 0.f, 0.f, 0.f);
            const int gp = g - 1;
            if (rowok && gp >= 0) {   // gp < 128 guaranteed (g <= 128)
                float4 a = x4[rb + gp], b = y4[rb + gp];
                prev.x = a.x - b.x; prev.y = a.y - b.y;
                prev.z = a.z - b.z; prev.w = a.w - b.w;
            }
        }
        if (g < GROUPS) {
            // h[c] = sum_{k=c-4..c} d(k); group g covers h[4g..4g+3]
            float4 hv;
            float p = prev.y + prev.z + prev.w;
            hv.x = prev.x + p + cur.x;
            hv.y = p + cur.x + cur.y;
            hv.z = prev.z + prev.w + cur.x + cur.y + cur.z;
            hv.w = prev.w + cur.x + cur.y + cur.z + cur.w;
            *reinterpret_cast<float4*>(hsm + ii * HP + 4 * g) = hv;
        }
    }
    __syncthreads();

    // ---- Phase 3: vertical 5-tap sliding sums + |.| accumulation (float4) ----
    float acc = 0.f;
    const int rmax = min(OUT_ROWS, OH - r0);
    if (tid < GROUPS) {
        const int t = tid;
        #define HROW(rr) (reinterpret_cast<const float4*>(hsm + (rr) * HP)[t])
        float4 h0 = HROW(0), h1 = HROW(1), h2 = HROW(2), h3 = HROW(3), h4 = HROW(4);
        float4 v;
        v.x = h0.x + h1.x + h2.x + h3.x + h4.x;
        v.y = h0.y + h1.y + h2.y + h3.y + h4.y;
        v.z = h0.z + h1.z + h2.z + h3.z + h4.z;
        v.w = h0.w + h1.w + h2.w + h3.w + h4.w;
        acc += fabsf(v.x) + fabsf(v.y) + fabsf(v.z) + fabsf(v.w);
        #pragma unroll 5
        for (int rr = 1; rr < rmax; ++rr) {
            float4 hn = HROW(rr + 4);
            float4 ho = HROW(rr - 1);
            v.x += hn.x - ho.x; v.y += hn.y - ho.y;
            v.z += hn.z - ho.z; v.w += hn.w - ho.w;
            acc += fabsf(v.x) + fabsf(v.y) + fabsf(v.z) + fabsf(v.w);
        }
        #undef HROW
    }

    // ---- Phase 4: block reduce + fused global finalize (last block writes) ----
    __shared__ float wsum[NWARPS];
    acc = warp_red(acc);
    if (lane == 0) wsum[wi] = acc;
    __syncthreads();
    if (tid == 0) {
        float v = wsum[0];
        #pragma unroll
        for (int i = 1; i < NWARPS; ++i) v += wsum[i];
        atomicAdd(&g_accum, (double)v);
        __threadfence();
        unsigned prev_cnt = atomicAdd(&g_count, 1u);
        if (prev_cnt == NBLOCKS - 1) {
            __threadfence();
            double total = atomicAdd(&g_accum, 0.0);  // serialized read
            const double scale = 1.0 / (25.0 * (double)B_IMGS * (double)OH * (double)OW);
            out[0] = (float)(total * scale);
            // reset for next graph replay
            g_accum = 0.0;
            __threadfence();
            g_count = 0u;
        }
    }
}

extern "C" void kernel_launch(void* const* d_in, const int* in_sizes, int n_in,
                              void* d_out, int out_size) {
    (void)in_sizes; (void)n_in; (void)out_size;
    const float* x = (const float*)d_in[0];
    const float* y = (const float*)d_in[1];
    float* out = (float*)d_out;

    dim3 grid(ROW_TILES, B_IMGS);
    box_abs_kernel<<<grid, THREADS, SMEM_BYTES>>>(x, y, out);
}

// round 3
// speedup vs baseline: 1.5699x; 1.3669x over previous
#include <cuda_runtime.h>
#include <cuda_bf16.h>

// DataWindowLoss: mean(|box5(x) - box5(y)|), x,y: [64,1,512,512] f32.
// box5(x)-box5(y) = box5(x-y); separable 5x5 uniform kernel.
// Register-streaming design: thread = one float4 column-group; per row:
//   load d (float4), horizontal 5-sum via shfl_up, vertical 5-row sliding
//   sum kept in a register ring (unroll-5 => static slots). No smem tile,
//   no syncthreads in the hot path. Cols 512..515 handled by edge blocks.

#define B_IMGS 64
#define H 512
#define W 512
#define OH 516
#define OW 516

#define THREADS 128
#define CHUNKS 12
#define ROWS_PER_CHUNK 43          // 12*43 = 516
#define SCAN 47                    // ROWS_PER_CHUNK + 4 halo rows
#define NBLOCKS ((CHUNKS + 1) * B_IMGS)   // 832 (incl. edge blocks)

__device__ double g_accum;      // zero-initialized
__device__ unsigned g_count;    // zero-initialized

__device__ __forceinline__ float warp_red(float v) {
    #pragma unroll
    for (int o = 16; o > 0; o >>= 1) v += __shfl_down_sync(0xffffffffu, v, o);
    return v;
}

__device__ __forceinline__ float4 f4zero() { return make_float4(0.f, 0.f, 0.f, 0.f); }

__global__ void __launch_bounds__(THREADS)
box_abs_kernel(const float* __restrict__ x, const float* __restrict__ y,
               float* __restrict__ out) {
    const int tid  = threadIdx.x;
    const int lane = tid & 31;
    const int img  = blockIdx.y;
    const size_t ibase = (size_t)img * H * (W / 4);
    const float4* x4 = reinterpret_cast<const float4*>(x) + ibase;
    const float4* y4 = reinterpret_cast<const float4*>(y) + ibase;

    float acc = 0.f;

    if (blockIdx.x < CHUNKS) {
        // ---- main path: h-cols 0..511, thread tid owns float4 group tid ----
        const int g  = tid;                       // 0..127
        const int R0 = blockIdx.x * ROWS_PER_CHUNK;
        const int base_r = R0 - 4;

        float4 r0 = f4zero(), r1 = f4zero(), r2 = f4zero(),
               r3 = f4zero(), r4 = f4zero();
        float4 vs = f4zero();

        #define STEP(J, RING)                                                  \
        {                                                                      \
            const int i = ib + (J);                                            \
            if (i < SCAN) {                                                    \
                const int r = base_r + i;                                      \
                const bool rowok = (r >= 0) && (r < H);                        \
                float4 cur = f4zero();                                         \
                if (rowok) {                                                   \
                    float4 a = x4[(size_t)r * (W/4) + g];                      \
                    float4 b = y4[(size_t)r * (W/4) + g];                      \
                    cur.x = a.x - b.x; cur.y = a.y - b.y;                      \
                    cur.z = a.z - b.z; cur.w = a.w - b.w;                      \
                }                                                              \
                float4 prv;                                                    \
                prv.x = __shfl_up_sync(0xffffffffu, cur.x, 1);                 \
                prv.y = __shfl_up_sync(0xffffffffu, cur.y, 1);                 \
                prv.z = __shfl_up_sync(0xffffffffu, cur.z, 1);                 \
                prv.w = __shfl_up_sync(0xffffffffu, cur.w, 1);                 \
                if (lane == 0) {                                               \
                    prv = f4zero();                                            \
                    if (rowok && g > 0) {                                      \
                        float4 a = x4[(size_t)r * (W/4) + g - 1];              \
                        float4 b = y4[(size_t)r * (W/4) + g - 1];              \
                        prv.x = a.x - b.x; prv.y = a.y - b.y;                  \
                        prv.z = a.z - b.z; prv.w = a.w - b.w;                  \
                    }                                                          \
                }                                                              \
                float4 hv;                                                     \
                const float p23 = prv.z + prv.w;                               \
                const float c01 = cur.x + cur.y;                               \
                hv.x = prv.x + prv.y + p23 + cur.x;                            \
                hv.y = prv.y + p23 + c01;                                      \
                hv.z = p23 + c01 + cur.z;                                      \
                hv.w = prv.w + c01 + cur.z + cur.w;                            \
                vs.x += hv.x - RING.x; vs.y += hv.y - RING.y;                  \
                vs.z += hv.z - RING.z; vs.w += hv.w - RING.w;                  \
                RING = hv;                                                     \
                if (i >= 4)                                                    \
                    acc += fabsf(vs.x) + fabsf(vs.y) +                         \
                           fabsf(vs.z) + fabsf(vs.w);                          \
            }                                                                  \
        }

        #pragma unroll 1
        for (int ib = 0; ib < 50; ib += 5) {
            STEP(0, r0) STEP(1, r1) STEP(2, r2) STEP(3, r3) STEP(4, r4)
        }
        #undef STEP
    } else {
        // ---- edge path: output cols 512..515 (need only d-group 127) ----
        // thread t handles output rows [4t, 4t+4); thread 0 also [512, 516).
        for (int pass = 0; pass < 2; ++pass) {
            if (pass == 1 && tid != 0) break;
            const int a = (pass == 0) ? 4 * tid : 512;
            float hx[8], hy[8], hz[8], hw[8];
            #pragma unroll
            for (int k = 0; k < 8; ++k) {
                const int r = a - 4 + k;
                float4 d = f4zero();
                if (r >= 0 && r < H) {
                    float4 av = x4[(size_t)r * (W/4) + 127];
                    float4 bv = y4[(size_t)r * (W/4) + 127];
                    d.x = av.x - bv.x; d.y = av.y - bv.y;
                    d.z = av.z - bv.z; d.w = av.w - bv.w;
                }
                hx[k] = d.x + d.y + d.z + d.w;   // h[512]
                hy[k] = d.y + d.z + d.w;         // h[513]
                hz[k] = d.z + d.w;               // h[514]
                hw[k] = d.w;                     // h[515]
            }
            #pragma unroll
            for (int j = 0; j < 4; ++j) {
                float sx = 0.f, sy = 0.f, sz = 0.f, sw = 0.f;
                #pragma unroll
                for (int k = j; k < j + 5; ++k) {
                    sx += hx[k]; sy += hy[k]; sz += hz[k]; sw += hw[k];
                }
                acc += fabsf(sx) + fabsf(sy) + fabsf(sz) + fabsf(sw);
            }
        }
    }

    // ---- block reduce + fused finalize ----
    __shared__ float wsum[4];
    acc = warp_red(acc);
    if (lane == 0) wsum[tid >> 5] = acc;
    __syncthreads();
    if (tid == 0) {
        float v = wsum[0] + wsum[1] + wsum[2] + wsum[3];
        atomicAdd(&g_accum, (double)v);
        __threadfence();
        unsigned prev_cnt = atomicAdd(&g_count, 1u);
        if (prev_cnt == NBLOCKS - 1) {
            __threadfence();
            double total = atomicAdd(&g_accum, 0.0);
            const double scale = 1.0 / (25.0 * (double)B_IMGS * (double)OH * (double)OW);
            out[0] = (float)(total * scale);
            g_accum = 0.0;          // reset for next graph replay
            __threadfence();
            g_count = 0u;
        }
    }
}

extern "C" void kernel_launch(void* const* d_in, const int* in_sizes, int n_in,
                              void* d_out, int out_size) {
    (void)in_sizes; (void)n_in; (void)out_size;
    const float* x = (const float*)d_in[0];
    const float* y = (const float*)d_in[1];
    float* out = (float*)d_out;

    dim3 grid(CHUNKS + 1, B_IMGS);
    box_abs_kernel<<<grid, THREADS>>>(x, y, out);
}